// round 3
// baseline (speedup 1.0000x reference)
#include <cuda_runtime.h>

// Detection1D: B=64, N=131072, C=1. Decode + per-batch greedy NMS (TOP_K=10).
//
//   k_init   : zero per-batch candidate counters (graph-replay safe).
//   k_filter : decode only elements with score > 0.99 (provably a superset of
//              any possible selection unless <10 such candidates survive),
//              compact (x1,x2,score,idx) into a per-batch global shortlist.
//   k_nms    : one block per batch. Exact greedy NMS over the shortlist in
//              smem with jnp.argmax tie-breaking (lowest index on equal
//              score). If the shortlist overflows or exhausts before 10
//              selections, fall back to exact full-N scans (never triggered
//              for this data, but guarantees exact behavior in all cases).

#define NB 64
#define NN 131072          // 2^17
#define CAP 2048
#define TOPK 10
#define THRESH 0.99f

__device__ float4 g_cand[NB * CAP];
__device__ int    g_cnt[NB];

__global__ void k_init() {
    int t = threadIdx.x;           // 64 threads
    g_cnt[t] = 0;
    g_cand[t * CAP] = make_float4(0.f, 0.f, 0.f, 0.f);
}

__global__ void __launch_bounds__(256) k_filter(
    const float4* __restrict__ clf4,
    const float2* __restrict__ reg,
    const float2* __restrict__ prop)
{
    int t  = blockIdx.x * blockDim.x + threadIdx.x;
    int e0 = t * 4;
    float4 s4 = clf4[t];
    float ss[4] = { s4.x, s4.y, s4.z, s4.w };
#pragma unroll
    for (int j = 0; j < 4; j++) {
        float s = ss[j];
        if (s > THRESH) {
            int e = e0 + j;
            float2 r = reg[e];
            float2 p = prop[e];
            float w   = p.y - p.x;
            float ctr = p.x + 0.5f * w;
            float pc  = ctr + (r.x * 0.1f) * w;
            float pw  = expf(r.y * 0.2f) * w;
            float x1 = fminf(fmaxf(pc - 0.5f * pw, 0.0f), 416.0f);
            float x2 = fminf(fmaxf(pc + 0.5f * pw, 0.0f), 416.0f);
            if (x2 - x1 > 3.0f) {      // (s > 0.01 subsumed by s > 0.99)
                int b = e >> 17;
                int pos = atomicAdd(&g_cnt[b], 1);
                if (pos < CAP) {
                    unsigned idx = (unsigned)(e & (NN - 1));
                    g_cand[b * CAP + pos] =
                        make_float4(x1, x2, s, __uint_as_float(idx));
                }
            }
        }
    }
}

__global__ void __launch_bounds__(256) k_nms(
    const float*  __restrict__ clf,
    const float2* __restrict__ reg,
    const float2* __restrict__ prop,
    float*        __restrict__ out)
{
    const int b   = blockIdx.x;
    const int tid = threadIdx.x;

    __shared__ unsigned long long skey[CAP];
    __shared__ float sx1[CAP], sx2[CAP];
    __shared__ float selX1[TOPK], selX2[TOPK], selSc[TOPK];
    __shared__ unsigned selIdx[TOPK];
    __shared__ int s_nsel;
    __shared__ int s_mode;   // 0 = fast path, 1 = fallback needed, 2 = done (-1 rows)
    __shared__ unsigned long long r_key[8];
    __shared__ float r_x1[8], r_x2[8];

    int cnt = g_cnt[b];
    int m   = min(max(cnt, 0), CAP);
    if (tid == 0) { s_nsel = 0; s_mode = (cnt > CAP) ? 1 : 0; }

    for (int i = tid; i < m; i += 256) {
        float4 c = g_cand[b * CAP + i];
        unsigned idx = __float_as_uint(c.w);
        skey[i] = ((unsigned long long)__float_as_uint(c.z) << 32)
                | (unsigned long long)(0xFFFFFFFFu - idx);
        sx1[i] = c.x;
        sx2[i] = c.y;
    }
    __syncthreads();

    // ---------------- fast path: exact NMS over the shortlist ----------------
    for (int t = 0; t < TOPK; t++) {
        if (s_mode != 0) break;   // uniform: s_mode last written before a barrier

        unsigned long long best = 0ULL;
        float bx1 = 0.f, bx2 = 0.f;
        for (int i = tid; i < m; i += 256) {
            unsigned long long k = skey[i];
            if (k > best) { best = k; bx1 = sx1[i]; bx2 = sx2[i]; }
        }
#pragma unroll
        for (int o = 16; o > 0; o >>= 1) {
            unsigned long long k2 = __shfl_down_sync(0xFFFFFFFFu, best, o);
            float a2 = __shfl_down_sync(0xFFFFFFFFu, bx1, o);
            float b2 = __shfl_down_sync(0xFFFFFFFFu, bx2, o);
            if (k2 > best) { best = k2; bx1 = a2; bx2 = b2; }
        }
        if ((tid & 31) == 0) {
            int w = tid >> 5;
            r_key[w] = best; r_x1[w] = bx1; r_x2[w] = bx2;
        }
        __syncthreads();
        if (tid == 0) {
            best = 0ULL;
#pragma unroll
            for (int w = 0; w < 8; w++)
                if (r_key[w] > best) { best = r_key[w]; bx1 = r_x1[w]; bx2 = r_x2[w]; }
            if (best == 0ULL) {
                s_mode = 1;   // shortlist exhausted -> must consult full array
            } else {
                selSc[t]  = __uint_as_float((unsigned)(best >> 32));
                selIdx[t] = 0xFFFFFFFFu - (unsigned)(best & 0xFFFFFFFFu);
                selX1[t]  = bx1;
                selX2[t]  = bx2;
                s_nsel = t + 1;
            }
        }
        __syncthreads();
        if (s_mode != 0) break;

        float BX1 = selX1[t], BX2 = selX2[t];
        float blen = BX2 - BX1;
        unsigned bidx = selIdx[t];
        for (int i = tid; i < m; i += 256) {
            unsigned long long k = skey[i];
            if (k == 0ULL) continue;
            float x1 = sx1[i], x2 = sx2[i];
            float inter = fmaxf(fminf(x2, BX2) - fmaxf(x1, BX1), 0.0f);
            float uni   = (x2 - x1) + blen - inter + 1e-9f;
            unsigned idx = 0xFFFFFFFFu - (unsigned)(k & 0xFFFFFFFFu);
            if (inter / uni > 0.5f || idx == bidx) skey[i] = 0ULL;
        }
        __syncthreads();
    }

    // ---------------- fallback: exact full-N scans (rarely/never runs) -------
    __syncthreads();
    if (s_mode == 1) {
        const float*  clfb  = clf  + (size_t)b * NN;
        const float2* regb  = reg  + (size_t)b * NN;
        const float2* propb = prop + (size_t)b * NN;
        for (int t = s_nsel; t < TOPK; t++) {
            unsigned long long best = 0ULL;
            float bx1 = 0.f, bx2 = 0.f;
            for (int i = tid; i < NN; i += 256) {
                float s = clfb[i];
                if (s <= 0.01f) continue;
                float2 r = regb[i];
                float2 p = propb[i];
                float w   = p.y - p.x;
                float ctr = p.x + 0.5f * w;
                float pc  = ctr + (r.x * 0.1f) * w;
                float pw  = expf(r.y * 0.2f) * w;
                float x1 = fminf(fmaxf(pc - 0.5f * pw, 0.0f), 416.0f);
                float x2 = fminf(fmaxf(pc + 0.5f * pw, 0.0f), 416.0f);
                float len = x2 - x1;
                if (len <= 3.0f) continue;
                bool sup = false;
                for (int j = 0; j < t; j++) {
                    if ((unsigned)i == selIdx[j]) { sup = true; break; }
                    float inter = fmaxf(fminf(x2, selX2[j]) - fmaxf(x1, selX1[j]), 0.0f);
                    float uni   = len + (selX2[j] - selX1[j]) - inter + 1e-9f;
                    if (inter / uni > 0.5f) { sup = true; break; }
                }
                if (sup) continue;
                unsigned long long k =
                    ((unsigned long long)__float_as_uint(s) << 32)
                  | (unsigned long long)(0xFFFFFFFFu - (unsigned)i);
                if (k > best) { best = k; bx1 = x1; bx2 = x2; }
            }
#pragma unroll
            for (int o = 16; o > 0; o >>= 1) {
                unsigned long long k2 = __shfl_down_sync(0xFFFFFFFFu, best, o);
                float a2 = __shfl_down_sync(0xFFFFFFFFu, bx1, o);
                float b2 = __shfl_down_sync(0xFFFFFFFFu, bx2, o);
                if (k2 > best) { best = k2; bx1 = a2; bx2 = b2; }
            }
            if ((tid & 31) == 0) {
                int w = tid >> 5;
                r_key[w] = best; r_x1[w] = bx1; r_x2[w] = bx2;
            }
            __syncthreads();
            if (tid == 0) {
                best = 0ULL;
#pragma unroll
                for (int w = 0; w < 8; w++)
                    if (r_key[w] > best) { best = r_key[w]; bx1 = r_x1[w]; bx2 = r_x2[w]; }
                if (best == 0ULL) {
                    s_mode = 2;   // truly no candidates remain -> -1 rows
                } else {
                    selSc[t]  = __uint_as_float((unsigned)(best >> 32));
                    selIdx[t] = 0xFFFFFFFFu - (unsigned)(best & 0xFFFFFFFFu);
                    selX1[t]  = bx1;
                    selX2[t]  = bx2;
                    s_nsel = t + 1;
                }
            }
            __syncthreads();
            if (s_mode == 2) break;
        }
    }

    __syncthreads();
    if (tid < TOPK) {
        int t = tid;
        float a = -1.0f, c = -1.0f, s = -1.0f;
        if (t < s_nsel) { a = selX1[t]; c = selX2[t]; s = selSc[t]; }
        out[b * (TOPK * 3) + t * 3 + 0] = a;
        out[b * (TOPK * 3) + t * 3 + 1] = c;
        out[b * (TOPK * 3) + t * 3 + 2] = s;
    }
}

extern "C" void kernel_launch(void* const* d_in, const int* in_sizes, int n_in,
                              void* d_out, int out_size)
{
    const float*  clf  = (const float*)d_in[0];                 // (64,131072,1)
    const float2* reg  = (const float2*)d_in[1];                // (64,131072,2)
    const float2* prop = (const float2*)d_in[2];                // (64,131072,2)
    float* out = (float*)d_out;                                 // (64,10,3)

    k_init<<<1, 64>>>();
    k_filter<<<(NB * NN / 4) / 256, 256>>>((const float4*)clf, reg, prop);
    k_nms<<<NB, 256>>>(clf, reg, prop, out);
}

// round 5
// speedup vs baseline: 2.0313x; 2.0313x over previous
#include <cuda_runtime.h>

// Detection1D: B=64, N=131072, C=1. Decode + per-batch greedy NMS (TOP_K=10).
//
//   k_filter : pure stream over clf (float4). Candidates = score > 0.99
//              (provable superset of any selection unless <10 survive).
//              Block-aggregated compaction: one global atomicAdd per block.
//              Writes (score, idx) 8B records. No reg/prop traffic here.
//   k_nms    : one block per batch. Gathers + decodes only the shortlist,
//              applies length test, then exact greedy NMS in smem with
//              jnp.argmax tie-breaking ((score<<32)|~idx keys). Shortlist
//              overflow/exhaustion -> exact full-N fallback (never triggers
//              on this data; guarantees exactness always). Resets g_cnt at
//              the end so the next graph replay starts clean (initial state
//              is the static zero-init).

#define NB 64
#define NN 131072          // 2^17
#define CAP 2048
#define TOPK 10
#define THRESH 0.99f

__device__ float2 g_cand[NB * CAP];   // (score, idx-as-float-bits)
__device__ int    g_cnt[NB];          // static zero-init; k_nms re-zeros

__global__ void __launch_bounds__(256) k_filter(const float4* __restrict__ clf4)
{
    __shared__ int s_cnt, s_base;
    if (threadIdx.x == 0) s_cnt = 0;
    __syncthreads();

    const int t  = blockIdx.x * 256 + threadIdx.x;   // float4 index
    const int b  = blockIdx.x >> 7;                  // 128 blocks per batch
    const unsigned e0 = ((unsigned)t * 4u) & (NN - 1u);  // within-batch idx

    float4 s4 = clf4[t];
    float ss[4] = { s4.x, s4.y, s4.z, s4.w };

    float    csc[4];
    unsigned cid[4];
    int k = 0;
#pragma unroll
    for (int j = 0; j < 4; j++) {
        if (ss[j] > THRESH) { csc[k] = ss[j]; cid[k] = e0 + j; k++; }
    }

    int pos = 0;
    if (k) pos = atomicAdd(&s_cnt, k);               // shared-mem atomic
    __syncthreads();
    if (threadIdx.x == 0)
        s_base = (s_cnt > 0) ? atomicAdd(&g_cnt[b], s_cnt) : 0;  // 1 global atomic/block
    __syncthreads();

    const int base = s_base;
#pragma unroll
    for (int i = 0; i < 4; i++) {
        if (i < k) {
            int p = base + pos + i;
            if (p < CAP)
                g_cand[b * CAP + p] = make_float2(csc[i], __uint_as_float(cid[i]));
        }
    }
}

__global__ void __launch_bounds__(256) k_nms(
    const float*  __restrict__ clf,
    const float2* __restrict__ reg,
    const float2* __restrict__ prop,
    float*        __restrict__ out)
{
    const int b   = blockIdx.x;
    const int tid = threadIdx.x;

    __shared__ unsigned long long skey[CAP];
    __shared__ float sx1[CAP], sx2[CAP];
    __shared__ float selX1[TOPK], selX2[TOPK], selSc[TOPK];
    __shared__ unsigned selIdx[TOPK];
    __shared__ int s_nsel;
    __shared__ int s_mode;   // 0 = fast path, 1 = fallback needed, 2 = done
    __shared__ unsigned long long r_key[8];
    __shared__ float r_x1[8], r_x2[8];

    const int cnt = g_cnt[b];
    const int m   = min(max(cnt, 0), CAP);
    if (tid == 0) { s_nsel = 0; s_mode = (cnt > CAP) ? 1 : 0; }

    const float2* regb  = reg  + (size_t)b * NN;
    const float2* propb = prop + (size_t)b * NN;

    // Gather + decode shortlist into smem
    for (int i = tid; i < m; i += 256) {
        float2 c = g_cand[b * CAP + i];
        unsigned idx = __float_as_uint(c.y);
        float2 r = regb[idx];
        float2 p = propb[idx];
        float w   = p.y - p.x;
        float ctr = p.x + 0.5f * w;
        float pc  = ctr + (r.x * 0.1f) * w;
        float pw  = expf(r.y * 0.2f) * w;
        float x1 = fminf(fmaxf(pc - 0.5f * pw, 0.0f), 416.0f);
        float x2 = fminf(fmaxf(pc + 0.5f * pw, 0.0f), 416.0f);
        unsigned long long key = 0ULL;
        if (x2 - x1 > 3.0f)
            key = ((unsigned long long)__float_as_uint(c.x) << 32)
                | (unsigned long long)(0xFFFFFFFFu - idx);
        skey[i] = key;
        sx1[i]  = x1;
        sx2[i]  = x2;
    }
    __syncthreads();

    // ---------------- fast path: exact NMS over the shortlist ----------------
    for (int t = 0; t < TOPK; t++) {
        if (s_mode != 0) break;   // uniform: written only before a barrier

        unsigned long long best = 0ULL;
        float bx1 = 0.f, bx2 = 0.f;
        for (int i = tid; i < m; i += 256) {
            unsigned long long k = skey[i];
            if (k > best) { best = k; bx1 = sx1[i]; bx2 = sx2[i]; }
        }
#pragma unroll
        for (int o = 16; o > 0; o >>= 1) {
            unsigned long long k2 = __shfl_down_sync(0xFFFFFFFFu, best, o);
            float a2 = __shfl_down_sync(0xFFFFFFFFu, bx1, o);
            float b2 = __shfl_down_sync(0xFFFFFFFFu, bx2, o);
            if (k2 > best) { best = k2; bx1 = a2; bx2 = b2; }
        }
        if ((tid & 31) == 0) {
            int w = tid >> 5;
            r_key[w] = best; r_x1[w] = bx1; r_x2[w] = bx2;
        }
        __syncthreads();
        if (tid == 0) {
            best = 0ULL;
#pragma unroll
            for (int w = 0; w < 8; w++)
                if (r_key[w] > best) { best = r_key[w]; bx1 = r_x1[w]; bx2 = r_x2[w]; }
            if (best == 0ULL) {
                s_mode = 1;   // shortlist exhausted -> consult full array
            } else {
                selSc[t]  = __uint_as_float((unsigned)(best >> 32));
                selIdx[t] = 0xFFFFFFFFu - (unsigned)(best & 0xFFFFFFFFu);
                selX1[t]  = bx1;
                selX2[t]  = bx2;
                s_nsel = t + 1;
            }
        }
        __syncthreads();
        if (s_mode != 0) break;

        float BX1 = selX1[t], BX2 = selX2[t];
        float blen = BX2 - BX1;
        unsigned bidx = selIdx[t];
        for (int i = tid; i < m; i += 256) {
            unsigned long long k = skey[i];
            if (k == 0ULL) continue;
            float x1 = sx1[i], x2 = sx2[i];
            float inter = fmaxf(fminf(x2, BX2) - fmaxf(x1, BX1), 0.0f);
            float uni   = (x2 - x1) + blen - inter + 1e-9f;
            unsigned idx = 0xFFFFFFFFu - (unsigned)(k & 0xFFFFFFFFu);
            if (inter / uni > 0.5f || idx == bidx) skey[i] = 0ULL;
        }
        __syncthreads();
    }

    // ---------------- fallback: exact full-N scans (rarely/never runs) -------
    __syncthreads();
    if (s_mode == 1) {
        const float* clfb = clf + (size_t)b * NN;
        for (int t = s_nsel; t < TOPK; t++) {
            unsigned long long best = 0ULL;
            float bx1 = 0.f, bx2 = 0.f;
            for (int i = tid; i < NN; i += 256) {
                float s = clfb[i];
                if (s <= 0.01f) continue;
                float2 r = regb[i];
                float2 p = propb[i];
                float w   = p.y - p.x;
                float ctr = p.x + 0.5f * w;
                float pc  = ctr + (r.x * 0.1f) * w;
                float pw  = expf(r.y * 0.2f) * w;
                float x1 = fminf(fmaxf(pc - 0.5f * pw, 0.0f), 416.0f);
                float x2 = fminf(fmaxf(pc + 0.5f * pw, 0.0f), 416.0f);
                float len = x2 - x1;
                if (len <= 3.0f) continue;
                bool sup = false;
                for (int j = 0; j < t; j++) {
                    if ((unsigned)i == selIdx[j]) { sup = true; break; }
                    float inter = fmaxf(fminf(x2, selX2[j]) - fmaxf(x1, selX1[j]), 0.0f);
                    float uni   = len + (selX2[j] - selX1[j]) - inter + 1e-9f;
                    if (inter / uni > 0.5f) { sup = true; break; }
                }
                if (sup) continue;
                unsigned long long k =
                    ((unsigned long long)__float_as_uint(s) << 32)
                  | (unsigned long long)(0xFFFFFFFFu - (unsigned)i);
                if (k > best) { best = k; bx1 = x1; bx2 = x2; }
            }
#pragma unroll
            for (int o = 16; o > 0; o >>= 1) {
                unsigned long long k2 = __shfl_down_sync(0xFFFFFFFFu, best, o);
                float a2 = __shfl_down_sync(0xFFFFFFFFu, bx1, o);
                float b2 = __shfl_down_sync(0xFFFFFFFFu, bx2, o);
                if (k2 > best) { best = k2; bx1 = a2; bx2 = b2; }
            }
            if ((tid & 31) == 0) {
                int w = tid >> 5;
                r_key[w] = best; r_x1[w] = bx1; r_x2[w] = bx2;
            }
            __syncthreads();
            if (tid == 0) {
                best = 0ULL;
#pragma unroll
                for (int w = 0; w < 8; w++)
                    if (r_key[w] > best) { best = r_key[w]; bx1 = r_x1[w]; bx2 = r_x2[w]; }
                if (best == 0ULL) {
                    s_mode = 2;   // no candidates remain -> -1 rows
                } else {
                    selSc[t]  = __uint_as_float((unsigned)(best >> 32));
                    selIdx[t] = 0xFFFFFFFFu - (unsigned)(best & 0xFFFFFFFFu);
                    selX1[t]  = bx1;
                    selX2[t]  = bx2;
                    s_nsel = t + 1;
                }
            }
            __syncthreads();
            if (s_mode == 2) break;
        }
    }

    __syncthreads();
    if (tid < TOPK) {
        int t = tid;
        float a = -1.0f, c = -1.0f, s = -1.0f;
        if (t < s_nsel) { a = selX1[t]; c = selX2[t]; s = selSc[t]; }
        out[b * (TOPK * 3) + t * 3 + 0] = a;
        out[b * (TOPK * 3) + t * 3 + 1] = c;
        out[b * (TOPK * 3) + t * 3 + 2] = s;
    }
    if (tid == 0) g_cnt[b] = 0;   // clean state for next graph replay
}

extern "C" void kernel_launch(void* const* d_in, const int* in_sizes, int n_in,
                              void* d_out, int out_size)
{
    const float*  clf  = (const float*)d_in[0];                 // (64,131072,1)
    const float2* reg  = (const float2*)d_in[1];                // (64,131072,2)
    const float2* prop = (const float2*)d_in[2];                // (64,131072,2)
    float* out = (float*)d_out;                                 // (64,10,3)

    k_filter<<<NB * NN / 1024, 256>>>((const float4*)clf);
    k_nms<<<NB, 256>>>(clf, reg, prop, out);
}

// round 7
// speedup vs baseline: 2.3801x; 1.1718x over previous
#include <cuda_runtime.h>

// Detection1D: B=64, N=131072, C=1. Decode + per-batch greedy NMS (TOP_K=10).
//
//   k_filter : pure stream over clf (float4). Candidates = score > 0.999
//              (10th-order-statistic of 131072 uniforms ~ 0.99992, suppression
//              depth ~40 ~ 0.9997 -> provable superset of any greedy selection
//              unless the shortlist exhausts, which the fallback covers).
//              Block-aggregated compaction: one global atomicAdd per block.
//   k_nms    : one block (128 thr) per batch. All threads gather + decode the
//              ~131-entry shortlist into smem; then WARP 0 alone runs the 10
//              exact argmax+suppress rounds (no __syncthreads in rounds, only
//              __syncwarp). jnp.argmax tie-break via (score<<32)|~idx keys.
//              Shortlist overflow/exhaustion -> exact block-wide full-N
//              fallback. Resets g_cnt at the end (graph-replay clean).

#define NB 64
#define NN 131072          // 2^17
#define CAP 512
#define TOPK 10
#define THRESH 0.999f

__device__ float2 g_cand[NB * CAP];   // (score, idx-as-float-bits)
__device__ int    g_cnt[NB];          // static zero-init; k_nms re-zeros

__global__ void __launch_bounds__(256) k_filter(const float4* __restrict__ clf4)
{
    __shared__ int s_cnt, s_base;
    if (threadIdx.x == 0) s_cnt = 0;
    __syncthreads();

    const int t  = blockIdx.x * 256 + threadIdx.x;       // float4 index
    const int b  = blockIdx.x >> 7;                      // 128 blocks per batch
    const unsigned e0 = ((unsigned)t * 4u) & (NN - 1u);  // within-batch idx

    float4 s4 = clf4[t];
    float ss[4] = { s4.x, s4.y, s4.z, s4.w };

    float    csc[4];
    unsigned cid[4];
    int k = 0;
#pragma unroll
    for (int j = 0; j < 4; j++) {
        if (ss[j] > THRESH) { csc[k] = ss[j]; cid[k] = e0 + j; k++; }
    }

    int pos = 0;
    if (k) pos = atomicAdd(&s_cnt, k);                   // smem atomic
    __syncthreads();
    if (threadIdx.x == 0)
        s_base = (s_cnt > 0) ? atomicAdd(&g_cnt[b], s_cnt) : 0;  // 1 global atomic/block
    __syncthreads();

    const int base = s_base;
#pragma unroll
    for (int i = 0; i < 4; i++) {
        if (i < k) {
            int p = base + pos + i;
            if (p < CAP)
                g_cand[b * CAP + p] = make_float2(csc[i], __uint_as_float(cid[i]));
        }
    }
}

__global__ void __launch_bounds__(128) k_nms(
    const float*  __restrict__ clf,
    const float2* __restrict__ reg,
    const float2* __restrict__ prop,
    float*        __restrict__ out)
{
    const int b   = blockIdx.x;
    const int tid = threadIdx.x;

    __shared__ unsigned long long skey[CAP];
    __shared__ float sx1[CAP], sx2[CAP];
    __shared__ float selX1[TOPK], selX2[TOPK], selSc[TOPK];
    __shared__ unsigned selIdx[TOPK];
    __shared__ int s_nsel;
    __shared__ int s_mode;   // 0 = fast path done OK, 1 = fallback needed, 2 = done

    const int cnt = g_cnt[b];
    const int m   = min(max(cnt, 0), CAP);
    if (tid == 0) { s_nsel = 0; s_mode = (cnt > CAP) ? 1 : 0; }

    const float2* regb  = reg  + (size_t)b * NN;
    const float2* propb = prop + (size_t)b * NN;

    // All 128 threads: gather + decode shortlist into smem (~131 entries)
    for (int i = tid; i < m; i += 128) {
        float2 c = g_cand[b * CAP + i];
        unsigned idx = __float_as_uint(c.y);
        float2 r = regb[idx];
        float2 p = propb[idx];
        float w   = p.y - p.x;
        float ctr = p.x + 0.5f * w;
        float pc  = ctr + (r.x * 0.1f) * w;
        float pw  = expf(r.y * 0.2f) * w;
        float x1 = fminf(fmaxf(pc - 0.5f * pw, 0.0f), 416.0f);
        float x2 = fminf(fmaxf(pc + 0.5f * pw, 0.0f), 416.0f);
        unsigned long long key = 0ULL;
        if (x2 - x1 > 3.0f)
            key = ((unsigned long long)__float_as_uint(c.x) << 32)
                | (unsigned long long)(0xFFFFFFFFu - idx);
        skey[i] = key;
        sx1[i]  = x1;
        sx2[i]  = x2;
    }
    __syncthreads();

    // ---------- fast path: warp 0 runs all TOPK rounds, no block barriers ----
    if (tid < 32 && s_mode == 0) {
        const int lane = tid;
        int nsel = 0;
        for (int t = 0; t < TOPK; t++) {
            unsigned long long best = 0ULL;
            float bx1 = 0.f, bx2 = 0.f;
            for (int i = lane; i < m; i += 32) {
                unsigned long long k = skey[i];
                if (k > best) { best = k; bx1 = sx1[i]; bx2 = sx2[i]; }
            }
#pragma unroll
            for (int o = 16; o > 0; o >>= 1) {
                unsigned long long k2 = __shfl_down_sync(0xFFFFFFFFu, best, o);
                float a2 = __shfl_down_sync(0xFFFFFFFFu, bx1, o);
                float b2 = __shfl_down_sync(0xFFFFFFFFu, bx2, o);
                if (k2 > best) { best = k2; bx1 = a2; bx2 = b2; }
            }
            best = __shfl_sync(0xFFFFFFFFu, best, 0);
            bx1  = __shfl_sync(0xFFFFFFFFu, bx1, 0);
            bx2  = __shfl_sync(0xFFFFFFFFu, bx2, 0);
            if (best == 0ULL) break;              // shortlist exhausted (uniform)

            unsigned bidx = 0xFFFFFFFFu - (unsigned)(best & 0xFFFFFFFFu);
            if (lane == 0) {
                selSc[t]  = __uint_as_float((unsigned)(best >> 32));
                selIdx[t] = bidx;
                selX1[t]  = bx1;
                selX2[t]  = bx2;
            }
            nsel = t + 1;

            float blen = bx2 - bx1;
            for (int i = lane; i < m; i += 32) {
                unsigned long long k = skey[i];
                if (k == 0ULL) continue;
                float x1 = sx1[i], x2 = sx2[i];
                float inter = fmaxf(fminf(x2, bx2) - fmaxf(x1, bx1), 0.0f);
                float uni   = (x2 - x1) + blen - inter + 1e-9f;
                unsigned idx = 0xFFFFFFFFu - (unsigned)(k & 0xFFFFFFFFu);
                if (inter / uni > 0.5f || idx == bidx) skey[i] = 0ULL;
            }
            __syncwarp();
        }
        if (lane == 0) {
            s_nsel = nsel;
            if (nsel < TOPK) s_mode = 1;          // exhausted -> consult full array
        }
    }
    __syncthreads();

    // ---------- fallback: exact full-N scans (rarely/never runs) -------------
    if (s_mode == 1) {
        __shared__ unsigned long long r_key[4];
        __shared__ float r_x1[4], r_x2[4];
        const float* clfb = clf + (size_t)b * NN;
        for (int t = s_nsel; t < TOPK; t++) {
            unsigned long long best = 0ULL;
            float bx1 = 0.f, bx2 = 0.f;
            for (int i = tid; i < NN; i += 128) {
                float s = clfb[i];
                if (s <= 0.01f) continue;
                float2 r = regb[i];
                float2 p = propb[i];
                float w   = p.y - p.x;
                float ctr = p.x + 0.5f * w;
                float pc  = ctr + (r.x * 0.1f) * w;
                float pw  = expf(r.y * 0.2f) * w;
                float x1 = fminf(fmaxf(pc - 0.5f * pw, 0.0f), 416.0f);
                float x2 = fminf(fmaxf(pc + 0.5f * pw, 0.0f), 416.0f);
                float len = x2 - x1;
                if (len <= 3.0f) continue;
                bool sup = false;
                for (int j = 0; j < t; j++) {
                    if ((unsigned)i == selIdx[j]) { sup = true; break; }
                    float inter = fmaxf(fminf(x2, selX2[j]) - fmaxf(x1, selX1[j]), 0.0f);
                    float uni   = len + (selX2[j] - selX1[j]) - inter + 1e-9f;
                    if (inter / uni > 0.5f) { sup = true; break; }
                }
                if (sup) continue;
                unsigned long long k =
                    ((unsigned long long)__float_as_uint(s) << 32)
                  | (unsigned long long)(0xFFFFFFFFu - (unsigned)i);
                if (k > best) { best = k; bx1 = x1; bx2 = x2; }
            }
#pragma unroll
            for (int o = 16; o > 0; o >>= 1) {
                unsigned long long k2 = __shfl_down_sync(0xFFFFFFFFu, best, o);
                float a2 = __shfl_down_sync(0xFFFFFFFFu, bx1, o);
                float b2 = __shfl_down_sync(0xFFFFFFFFu, bx2, o);
                if (k2 > best) { best = k2; bx1 = a2; bx2 = b2; }
            }
            if ((tid & 31) == 0) {
                int w = tid >> 5;
                r_key[w] = best; r_x1[w] = bx1; r_x2[w] = bx2;
            }
            __syncthreads();
            if (tid == 0) {
                best = 0ULL;
#pragma unroll
                for (int w = 0; w < 4; w++)
                    if (r_key[w] > best) { best = r_key[w]; bx1 = r_x1[w]; bx2 = r_x2[w]; }
                if (best == 0ULL) {
                    s_mode = 2;   // nothing left -> -1 rows from here on
                } else {
                    selSc[t]  = __uint_as_float((unsigned)(best >> 32));
                    selIdx[t] = 0xFFFFFFFFu - (unsigned)(best & 0xFFFFFFFFu);
                    selX1[t]  = bx1;
                    selX2[t]  = bx2;
                    s_nsel = t + 1;
                }
            }
            __syncthreads();
            if (s_mode == 2) break;
        }
    }

    __syncthreads();
    if (tid < TOPK) {
        int t = tid;
        float a = -1.0f, c = -1.0f, s = -1.0f;
        if (t < s_nsel) { a = selX1[t]; c = selX2[t]; s = selSc[t]; }
        out[b * (TOPK * 3) + t * 3 + 0] = a;
        out[b * (TOPK * 3) + t * 3 + 1] = c;
        out[b * (TOPK * 3) + t * 3 + 2] = s;
    }
    if (tid == 0) g_cnt[b] = 0;   // clean state for next graph replay
}

extern "C" void kernel_launch(void* const* d_in, const int* in_sizes, int n_in,
                              void* d_out, int out_size)
{
    const float*  clf  = (const float*)d_in[0];                 // (64,131072,1)
    const float2* reg  = (const float2*)d_in[1];                // (64,131072,2)
    const float2* prop = (const float2*)d_in[2];                // (64,131072,2)
    float* out = (float*)d_out;                                 // (64,10,3)

    k_filter<<<NB * NN / 1024, 256>>>((const float4*)clf);
    k_nms<<<NB, 128>>>(clf, reg, prop, out);
}